// round 4
// baseline (speedup 1.0000x reference)
#include <cuda_runtime.h>
#include <cuda_bf16.h>
#include <cstdint>

#define DEVINL __device__ __forceinline__

namespace {

constexpr int BATCH = 32;
constexpr int LSEQ  = 8192;
constexpr int TM    = 128;                   // Q rows per CTA
constexpr int THREADS = 256;                 // 8 warps x 16 rows
constexpr int GRID = BATCH * (LSEQ / TM);    // 2048

// ---- SMEM layout (bytes). All tiles: 128x128 bf16, 256B row stride, XOR-swizzled.
constexpr int SM_QSUM = 0;                   // 128 floats
constexpr int SM_KSUM = 512;                 // 128 floats
constexpr int SM_QH = 1024;
constexpr int SM_QL = SM_QH + 32768;
constexpr int SM_KH = SM_QL + 32768;
constexpr int SM_KL = SM_KH + 32768;
constexpr int SM_VH = SM_KL + 32768;
constexpr int SM_VL = SM_VH + 32768;
constexpr int SMEM_TOTAL = SM_VL + 32768;    // 197632 B

// byte offset of bf16 element (r, c) in a 128x128 tile; 16B-chunk XOR swizzle
DEVINL uint32_t swz(int r, int c) {
    return (uint32_t)((r << 8) | ((((c >> 3) ^ (r & 7)) << 4) | ((c & 7) << 1)));
}

DEVINL uint32_t smem_u32(const void* p) {
    uint32_t a;
    asm("{ .reg .u64 t; cvta.to.shared.u64 t, %1; cvt.u32.u64 %0, t; }" : "=r"(a) : "l"(p));
    return a;
}

DEVINL uint32_t packb(__nv_bfloat16 a, __nv_bfloat16 b) {
    return (uint32_t)__bfloat16_as_ushort(a) | ((uint32_t)__bfloat16_as_ushort(b) << 16);
}

// split x = hi + lo (bf16 each), pack pairs
DEVINL void split_pack2(float a, float b, uint32_t& h, uint32_t& l) {
    __nv_bfloat16 ha = __float2bfloat16_rn(a), hb = __float2bfloat16_rn(b);
    __nv_bfloat16 la = __float2bfloat16_rn(a - __bfloat162float(ha));
    __nv_bfloat16 lb = __float2bfloat16_rn(b - __bfloat162float(hb));
    h = packb(ha, hb);
    l = packb(la, lb);
}

// ldmatrix x4 address: 4 8x8 matrices (rows rbase..+15, 16 cols from c8base*8)
DEVINL uint32_t ldsm_addr(uint32_t tbase, int rbase, int c8base, int lane) {
    int ln = lane & 7, sel = lane >> 3;
    int r  = rbase + ln + ((sel & 1) << 3);
    int c8 = c8base + (sel >> 1);
    return tbase + swz(r, c8 << 3);
}

DEVINL void ldsm4(uint32_t a[4], uint32_t addr) {
    asm volatile("ldmatrix.sync.aligned.m8n8.x4.shared.b16 {%0,%1,%2,%3}, [%4];"
                 : "=r"(a[0]), "=r"(a[1]), "=r"(a[2]), "=r"(a[3]) : "r"(addr));
}
DEVINL void ldsm4t(uint32_t a[4], uint32_t addr) {
    asm volatile("ldmatrix.sync.aligned.m8n8.x4.trans.shared.b16 {%0,%1,%2,%3}, [%4];"
                 : "=r"(a[0]), "=r"(a[1]), "=r"(a[2]), "=r"(a[3]) : "r"(addr));
}

DEVINL void mma_bf16(float c[4], const uint32_t a[4], uint32_t b0, uint32_t b1) {
    asm volatile(
        "mma.sync.aligned.m16n8k16.row.col.f32.bf16.bf16.f32 "
        "{%0,%1,%2,%3}, {%4,%5,%6,%7}, {%8,%9}, {%0,%1,%2,%3};"
        : "+f"(c[0]), "+f"(c[1]), "+f"(c[2]), "+f"(c[3])
        : "r"(a[0]), "r"(a[1]), "r"(a[2]), "r"(a[3]), "r"(b0), "r"(b1));
}

// fill one 128x128 tile: global fp32 -> bf16 hi/lo into swizzled SMEM.
// thread handles half a row (64 floats). Optionally produces exact fp32 row sums.
DEVINL void fill_tile(const float* __restrict__ src, char* smem, int offH, int offL,
                      int tid, float* rowsum) {
    const int row = tid >> 1;
    const int cb  = (tid & 1) << 6;
    const float4* p = reinterpret_cast<const float4*>(src + row * 128 + cb);
    float s = 0.f;
    #pragma unroll
    for (int i = 0; i < 16; i++) {
        float4 t = p[i];
        s += (t.x + t.y) + (t.z + t.w);
        uint32_t h01, l01, h23, l23;
        split_pack2(t.x, t.y, h01, l01);
        split_pack2(t.z, t.w, h23, l23);
        uint32_t off = swz(row, cb + i * 4);
        *reinterpret_cast<uint2*>(smem + offH + off) = make_uint2(h01, h23);
        *reinterpret_cast<uint2*>(smem + offL + off) = make_uint2(l01, l23);
    }
    if (rowsum) {
        s += __shfl_xor_sync(0xffffffffu, s, 1);
        if ((tid & 1) == 0) rowsum[row] = s;
    }
}

__global__ void __launch_bounds__(THREADS, 1)
axial_attn_kernel(const float* __restrict__ q, const float* __restrict__ k,
                  const float* __restrict__ v, float* __restrict__ out) {
    extern __shared__ char smem[];
    const uint32_t sb = smem_u32(smem);
    const int tid = threadIdx.x;

    const int b  = blockIdx.x >> 6;
    const int l0 = (blockIdx.x & 63) * TM;

    float* qsum = reinterpret_cast<float*>(smem + SM_QSUM);
    float* ksum = reinterpret_cast<float*>(smem + SM_KSUM);

    const float* qb = q + ((size_t)b * LSEQ + l0) * 128;
    const float* kb = k + (size_t)b * (128 * 128);
    const float* vb = v + (size_t)b * (128 * 128);

    // scores = Q @ K  (+ exact rank-1 qsum x ksum added post-MMA)
    fill_tile(qb, smem, SM_QH, SM_QL, tid, qsum);
    fill_tile(kb, smem, SM_KH, SM_KL, tid, ksum);   // ksum[j] = sum_d k[j][d]
    fill_tile(vb, smem, SM_VH, SM_VL, tid, nullptr);
    __syncthreads();

    const int lane = tid & 31, w = tid >> 5;
    const int g = lane >> 2, t = lane & 3;

    // ---- Q A-fragments (hi/lo), 8 k-tiles ----
    uint32_t aqh[8][4], aql[8][4];
    #pragma unroll
    for (int kk = 0; kk < 8; kk++) {
        ldsm4(aqh[kk], ldsm_addr(sb + SM_QH, 16 * w, 2 * kk, lane));
        ldsm4(aql[kk], ldsm_addr(sb + SM_QL, 16 * w, 2 * kk, lane));
    }

    // ---- GEMM1: S = Qh*Kh + Qh*Kl + Ql*Kh ----
    float C1[16][4];
    #pragma unroll
    for (int jt = 0; jt < 16; jt++)
        #pragma unroll
        for (int i = 0; i < 4; i++) C1[jt][i] = 0.f;

    #pragma unroll
    for (int jp = 0; jp < 8; jp++) {
        #pragma unroll
        for (int kk = 0; kk < 8; kk++) {
            uint32_t bh[4], bl[4];
            ldsm4t(bh, ldsm_addr(sb + SM_KH, 16 * kk, 2 * jp, lane));
            ldsm4t(bl, ldsm_addr(sb + SM_KL, 16 * kk, 2 * jp, lane));
            mma_bf16(C1[2 * jp],     aqh[kk], bh[0], bh[1]);
            mma_bf16(C1[2 * jp + 1], aqh[kk], bh[2], bh[3]);
            mma_bf16(C1[2 * jp],     aqh[kk], bl[0], bl[1]);
            mma_bf16(C1[2 * jp + 1], aqh[kk], bl[2], bl[3]);
            mma_bf16(C1[2 * jp],     aql[kk], bh[0], bh[1]);
            mma_bf16(C1[2 * jp + 1], aql[kk], bh[2], bh[3]);
        }
    }

    // ---- exact rank-1 term: += qsum[row] * ksum[col] ----
    const float qs_lo = qsum[16 * w + g];
    const float qs_hi = qsum[16 * w + g + 8];
    #pragma unroll
    for (int jt = 0; jt < 16; jt++) {
        float2 ks2 = *reinterpret_cast<const float2*>(ksum + 8 * jt + 2 * t);
        C1[jt][0] += qs_lo * ks2.x;
        C1[jt][1] += qs_lo * ks2.y;
        C1[jt][2] += qs_hi * ks2.x;
        C1[jt][3] += qs_hi * ks2.y;
    }

    // ---- softmax (rows g and g+8; quad = 4 lanes share a row) ----
    float mlo = -3.4e38f, mhi = -3.4e38f;
    #pragma unroll
    for (int jt = 0; jt < 16; jt++) {
        mlo = fmaxf(mlo, fmaxf(C1[jt][0], C1[jt][1]));
        mhi = fmaxf(mhi, fmaxf(C1[jt][2], C1[jt][3]));
    }
    mlo = fmaxf(mlo, __shfl_xor_sync(0xffffffffu, mlo, 1));
    mlo = fmaxf(mlo, __shfl_xor_sync(0xffffffffu, mlo, 2));
    mhi = fmaxf(mhi, __shfl_xor_sync(0xffffffffu, mhi, 1));
    mhi = fmaxf(mhi, __shfl_xor_sync(0xffffffffu, mhi, 2));

    float slo = 0.f, shi = 0.f;
    #pragma unroll
    for (int jt = 0; jt < 16; jt++) {
        C1[jt][0] = __expf(C1[jt][0] - mlo);
        C1[jt][1] = __expf(C1[jt][1] - mlo);
        C1[jt][2] = __expf(C1[jt][2] - mhi);
        C1[jt][3] = __expf(C1[jt][3] - mhi);
        slo += C1[jt][0] + C1[jt][1];
        shi += C1[jt][2] + C1[jt][3];
    }
    slo += __shfl_xor_sync(0xffffffffu, slo, 1);
    slo += __shfl_xor_sync(0xffffffffu, slo, 2);
    shi += __shfl_xor_sync(0xffffffffu, shi, 1);
    shi += __shfl_xor_sync(0xffffffffu, shi, 2);
    const float inv_lo = 1.0f / slo;
    const float inv_hi = 1.0f / shi;

    // ---- convert P (C-fragments) to A-fragments in registers (hi/lo) ----
    uint32_t ah[8][4], al[8][4];
    #pragma unroll
    for (int kk = 0; kk < 8; kk++) {
        split_pack2(C1[2 * kk][0],     C1[2 * kk][1],     ah[kk][0], al[kk][0]);
        split_pack2(C1[2 * kk][2],     C1[2 * kk][3],     ah[kk][1], al[kk][1]);
        split_pack2(C1[2 * kk + 1][0], C1[2 * kk + 1][1], ah[kk][2], al[kk][2]);
        split_pack2(C1[2 * kk + 1][2], C1[2 * kk + 1][3], ah[kk][3], al[kk][3]);
    }

    // ---- GEMM2: O = Ph*Vh + Ph*Vl + Pl*Vh ----
    float C2[16][4];
    #pragma unroll
    for (int jt = 0; jt < 16; jt++)
        #pragma unroll
        for (int i = 0; i < 4; i++) C2[jt][i] = 0.f;

    #pragma unroll
    for (int jp = 0; jp < 8; jp++) {
        #pragma unroll
        for (int kk = 0; kk < 8; kk++) {
            uint32_t bh[4], bl[4];
            ldsm4t(bh, ldsm_addr(sb + SM_VH, 16 * kk, 2 * jp, lane));
            ldsm4t(bl, ldsm_addr(sb + SM_VL, 16 * kk, 2 * jp, lane));
            mma_bf16(C2[2 * jp],     ah[kk], bh[0], bh[1]);
            mma_bf16(C2[2 * jp + 1], ah[kk], bh[2], bh[3]);
            mma_bf16(C2[2 * jp],     ah[kk], bl[0], bl[1]);
            mma_bf16(C2[2 * jp + 1], ah[kk], bl[2], bl[3]);
            mma_bf16(C2[2 * jp],     al[kk], bh[0], bh[1]);
            mma_bf16(C2[2 * jp + 1], al[kk], bh[2], bh[3]);
        }
    }

    // ---- store (normalize by 1/rowsum here) ----
    float* ob = out + ((size_t)b * LSEQ + l0 + 16 * w) * 128;
    #pragma unroll
    for (int jt = 0; jt < 16; jt++) {
        const int col = 8 * jt + 2 * t;
        *reinterpret_cast<float2*>(ob + (size_t)g * 128 + col) =
            make_float2(C2[jt][0] * inv_lo, C2[jt][1] * inv_lo);
        *reinterpret_cast<float2*>(ob + (size_t)(g + 8) * 128 + col) =
            make_float2(C2[jt][2] * inv_hi, C2[jt][3] * inv_hi);
    }
}

} // anonymous namespace

extern "C" void kernel_launch(void* const* d_in, const int* in_sizes, int n_in,
                              void* d_out, int out_size) {
    const float* q = (const float*)d_in[0];
    const float* k = (const float*)d_in[1];
    const float* v = (const float*)d_in[2];
    float* out = (float*)d_out;

    cudaFuncSetAttribute(axial_attn_kernel,
                         cudaFuncAttributeMaxDynamicSharedMemorySize, SMEM_TOTAL);
    axial_attn_kernel<<<GRID, THREADS, SMEM_TOTAL>>>(q, k, v, out);
}

// round 5
// speedup vs baseline: 1.1181x; 1.1181x over previous
#include <cuda_runtime.h>
#include <cuda_fp16.h>
#include <cstdint>

#define DEVINL __device__ __forceinline__

namespace {

constexpr int BATCH = 32;
constexpr int LSEQ  = 8192;
constexpr int TM    = 64;                    // Q rows per CTA
constexpr int THREADS = 128;                 // 4 warps x 16 rows
constexpr int GRID = BATCH * (LSEQ / TM);    // 4096

// ---- SMEM layout (bytes). Tiles: 128x128 fp16, 256B row stride, XOR-swizzled.
constexpr int SM_KSUM = 0;                   // 128 floats
constexpr int SM_KH = 1024;
constexpr int SM_KL = SM_KH + 32768;
constexpr int SM_VH = SM_KL + 32768;
constexpr int SMEM_TOTAL = SM_VH + 32768;    // 99328 B -> 2 CTAs/SM

// byte offset of fp16 element (r, c) in a 128x128 tile; 16B-chunk XOR swizzle
DEVINL uint32_t swz(int r, int c) {
    return (uint32_t)((r << 8) | ((((c >> 3) ^ (r & 7)) << 4) | ((c & 7) << 1)));
}

DEVINL uint32_t smem_u32(const void* p) {
    uint32_t a;
    asm("{ .reg .u64 t; cvta.to.shared.u64 t, %1; cvt.u32.u64 %0, t; }" : "=r"(a) : "l"(p));
    return a;
}

DEVINL uint32_t packh(__half a, __half b) {
    return (uint32_t)__half_as_ushort(a) | ((uint32_t)__half_as_ushort(b) << 16);
}

// split (a,b) into fp16 hi + fp16 lo, packed
DEVINL void split_pack2h(float a, float b, uint32_t& h, uint32_t& l) {
    __half ha = __float2half_rn(a), hb = __float2half_rn(b);
    __half la = __float2half_rn(a - __half2float(ha));
    __half lb = __float2half_rn(b - __half2float(hb));
    h = packh(ha, hb);
    l = packh(la, lb);
}
DEVINL uint32_t pack_hi2(float a, float b) {
    return packh(__float2half_rn(a), __float2half_rn(b));
}

// ldmatrix x4 address: 4 8x8 matrices (rows rbase..+15, 16 cols from c8base*8)
DEVINL uint32_t ldsm_addr(uint32_t tbase, int rbase, int c8base, int lane) {
    int ln = lane & 7, sel = lane >> 3;
    int r  = rbase + ln + ((sel & 1) << 3);
    int c8 = c8base + (sel >> 1);
    return tbase + swz(r, c8 << 3);
}

DEVINL void ldsm4t(uint32_t a[4], uint32_t addr) {
    asm volatile("ldmatrix.sync.aligned.m8n8.x4.trans.shared.b16 {%0,%1,%2,%3}, [%4];"
                 : "=r"(a[0]), "=r"(a[1]), "=r"(a[2]), "=r"(a[3]) : "r"(addr));
}

DEVINL void mma_fp16(float c[4], const uint32_t a[4], uint32_t b0, uint32_t b1) {
    asm volatile(
        "mma.sync.aligned.m16n8k16.row.col.f32.f16.f16.f32 "
        "{%0,%1,%2,%3}, {%4,%5,%6,%7}, {%8,%9}, {%0,%1,%2,%3};"
        : "+f"(c[0]), "+f"(c[1]), "+f"(c[2]), "+f"(c[3])
        : "r"(a[0]), "r"(a[1]), "r"(a[2]), "r"(a[3]), "r"(b0), "r"(b1));
}

__global__ void __launch_bounds__(THREADS, 2)
axial_attn_kernel(const float* __restrict__ q, const float* __restrict__ k,
                  const float* __restrict__ v, float* __restrict__ out) {
    extern __shared__ char smem[];
    const uint32_t sb = smem_u32(smem);
    const int tid  = threadIdx.x;
    const int lane = tid & 31, w = tid >> 5;
    const int g = lane >> 2, t = lane & 3;

    const int b  = blockIdx.x >> 7;
    const int l0 = (blockIdx.x & 127) * TM;

    float* ksum = reinterpret_cast<float*>(smem + SM_KSUM);

    const float* kb = k + (size_t)b * (128 * 128);
    const float* vb = v + (size_t)b * (128 * 128);

    // ---- Q: load A-fragment elements straight from GMEM (sector-coalesced) ----
    // lane needs rows (16w+g, 16w+g+8), cols 2t + 8j, j = 0..15
    const float* qrow0 = q + ((size_t)b * LSEQ + l0 + 16 * w + g) * 128 + 2 * t;
    const float* qrow1 = qrow0 + 8 * 128;
    float2 q0[16], q1[16];
    #pragma unroll
    for (int j = 0; j < 16; j++) {
        q0[j] = *reinterpret_cast<const float2*>(qrow0 + 8 * j);
        q1[j] = *reinterpret_cast<const float2*>(qrow1 + 8 * j);
    }

    // ---- K fill: fp32 -> fp16 hi/lo swizzled SMEM + exact fp32 row sums ----
    {
        const float4* kb4 = reinterpret_cast<const float4*>(kb);
        #pragma unroll 4
        for (int it = 0; it < 32; it++) {
            int e4  = it * THREADS + tid;          // warp covers exactly one row
            int row = e4 >> 5;
            int col = (e4 & 31) << 2;
            float4 tk = kb4[e4];
            uint32_t h01, l01, h23, l23;
            split_pack2h(tk.x, tk.y, h01, l01);
            split_pack2h(tk.z, tk.w, h23, l23);
            uint32_t off = swz(row, col);
            *reinterpret_cast<uint2*>(smem + SM_KH + off) = make_uint2(h01, h23);
            *reinterpret_cast<uint2*>(smem + SM_KL + off) = make_uint2(l01, l23);
            float s = (tk.x + tk.y) + (tk.z + tk.w);
            s += __shfl_xor_sync(0xffffffffu, s, 16);
            s += __shfl_xor_sync(0xffffffffu, s, 8);
            s += __shfl_xor_sync(0xffffffffu, s, 4);
            s += __shfl_xor_sync(0xffffffffu, s, 2);
            s += __shfl_xor_sync(0xffffffffu, s, 1);
            if (lane == 0) ksum[row] = s;
        }
    }
    // ---- V fill: fp16 hi only ----
    {
        const float4* vb4 = reinterpret_cast<const float4*>(vb);
        #pragma unroll 4
        for (int it = 0; it < 32; it++) {
            int e4  = it * THREADS + tid;
            int row = e4 >> 5;
            int col = (e4 & 31) << 2;
            float4 tv = vb4[e4];
            uint32_t off = swz(row, col);
            *reinterpret_cast<uint2*>(smem + SM_VH + off) =
                make_uint2(pack_hi2(tv.x, tv.y), pack_hi2(tv.z, tv.w));
        }
    }

    // ---- qsum (exact fp32, reduced within quad) + Q fragments hi/lo ----
    float qs_lo = 0.f, qs_hi = 0.f;
    #pragma unroll
    for (int j = 0; j < 16; j++) {
        qs_lo += q0[j].x + q0[j].y;
        qs_hi += q1[j].x + q1[j].y;
    }
    qs_lo += __shfl_xor_sync(0xffffffffu, qs_lo, 1);
    qs_lo += __shfl_xor_sync(0xffffffffu, qs_lo, 2);
    qs_hi += __shfl_xor_sync(0xffffffffu, qs_hi, 1);
    qs_hi += __shfl_xor_sync(0xffffffffu, qs_hi, 2);

    uint32_t aqh[8][4], aql[8][4];
    #pragma unroll
    for (int kk = 0; kk < 8; kk++) {
        split_pack2h(q0[2 * kk].x,     q0[2 * kk].y,     aqh[kk][0], aql[kk][0]);
        split_pack2h(q1[2 * kk].x,     q1[2 * kk].y,     aqh[kk][1], aql[kk][1]);
        split_pack2h(q0[2 * kk + 1].x, q0[2 * kk + 1].y, aqh[kk][2], aql[kk][2]);
        split_pack2h(q1[2 * kk + 1].x, q1[2 * kk + 1].y, aqh[kk][3], aql[kk][3]);
    }
    __syncthreads();

    // ---- GEMM1: S = Qh*Kh + Qh*Kl + Ql*Kh  (fp16 3-term) ----
    float C1[16][4];
    #pragma unroll
    for (int jt = 0; jt < 16; jt++)
        #pragma unroll
        for (int i = 0; i < 4; i++) C1[jt][i] = 0.f;

    #pragma unroll
    for (int jp = 0; jp < 8; jp++) {
        #pragma unroll
        for (int kk = 0; kk < 8; kk++) {
            uint32_t bh[4], bl[4];
            ldsm4t(bh, ldsm_addr(sb + SM_KH, 16 * kk, 2 * jp, lane));
            ldsm4t(bl, ldsm_addr(sb + SM_KL, 16 * kk, 2 * jp, lane));
            mma_fp16(C1[2 * jp],     aqh[kk], bh[0], bh[1]);
            mma_fp16(C1[2 * jp + 1], aqh[kk], bh[2], bh[3]);
            mma_fp16(C1[2 * jp],     aqh[kk], bl[0], bl[1]);
            mma_fp16(C1[2 * jp + 1], aqh[kk], bl[2], bl[3]);
            mma_fp16(C1[2 * jp],     aql[kk], bh[0], bh[1]);
            mma_fp16(C1[2 * jp + 1], aql[kk], bh[2], bh[3]);
        }
    }

    // ---- exact rank-1 term: += qsum[row] * ksum[col] ----
    #pragma unroll
    for (int jt = 0; jt < 16; jt++) {
        float2 ks2 = *reinterpret_cast<const float2*>(ksum + 8 * jt + 2 * t);
        C1[jt][0] += qs_lo * ks2.x;
        C1[jt][1] += qs_lo * ks2.y;
        C1[jt][2] += qs_hi * ks2.x;
        C1[jt][3] += qs_hi * ks2.y;
    }

    // ---- softmax (rows g and g+8; quad shares a row) ----
    float mlo = -3.4e38f, mhi = -3.4e38f;
    #pragma unroll
    for (int jt = 0; jt < 16; jt++) {
        mlo = fmaxf(mlo, fmaxf(C1[jt][0], C1[jt][1]));
        mhi = fmaxf(mhi, fmaxf(C1[jt][2], C1[jt][3]));
    }
    mlo = fmaxf(mlo, __shfl_xor_sync(0xffffffffu, mlo, 1));
    mlo = fmaxf(mlo, __shfl_xor_sync(0xffffffffu, mlo, 2));
    mhi = fmaxf(mhi, __shfl_xor_sync(0xffffffffu, mhi, 1));
    mhi = fmaxf(mhi, __shfl_xor_sync(0xffffffffu, mhi, 2));

    float slo = 0.f, shi = 0.f;
    #pragma unroll
    for (int jt = 0; jt < 16; jt++) {
        C1[jt][0] = __expf(C1[jt][0] - mlo);
        C1[jt][1] = __expf(C1[jt][1] - mlo);
        C1[jt][2] = __expf(C1[jt][2] - mhi);
        C1[jt][3] = __expf(C1[jt][3] - mhi);
        slo += C1[jt][0] + C1[jt][1];
        shi += C1[jt][2] + C1[jt][3];
    }
    slo += __shfl_xor_sync(0xffffffffu, slo, 1);
    slo += __shfl_xor_sync(0xffffffffu, slo, 2);
    shi += __shfl_xor_sync(0xffffffffu, shi, 1);
    shi += __shfl_xor_sync(0xffffffffu, shi, 2);
    const float inv_lo = 1.0f / slo;
    const float inv_hi = 1.0f / shi;

    // ---- P -> A-fragments (fp16 hi/lo) in registers ----
    uint32_t ah[8][4], al[8][4];
    #pragma unroll
    for (int kk = 0; kk < 8; kk++) {
        split_pack2h(C1[2 * kk][0],     C1[2 * kk][1],     ah[kk][0], al[kk][0]);
        split_pack2h(C1[2 * kk][2],     C1[2 * kk][3],     ah[kk][1], al[kk][1]);
        split_pack2h(C1[2 * kk + 1][0], C1[2 * kk + 1][1], ah[kk][2], al[kk][2]);
        split_pack2h(C1[2 * kk + 1][2], C1[2 * kk + 1][3], ah[kk][3], al[kk][3]);
    }

    // ---- GEMM2: O = (Ph + Pl) @ Vh ----
    float C2[16][4];
    #pragma unroll
    for (int jt = 0; jt < 16; jt++)
        #pragma unroll
        for (int i = 0; i < 4; i++) C2[jt][i] = 0.f;

    #pragma unroll
    for (int jp = 0; jp < 8; jp++) {
        #pragma unroll
        for (int kk = 0; kk < 8; kk++) {
            uint32_t bh[4];
            ldsm4t(bh, ldsm_addr(sb + SM_VH, 16 * kk, 2 * jp, lane));
            mma_fp16(C2[2 * jp],     ah[kk], bh[0], bh[1]);
            mma_fp16(C2[2 * jp + 1], ah[kk], bh[2], bh[3]);
            mma_fp16(C2[2 * jp],     al[kk], bh[0], bh[1]);
            mma_fp16(C2[2 * jp + 1], al[kk], bh[2], bh[3]);
        }
    }

    // ---- store (normalize here) ----
    float* ob = out + ((size_t)b * LSEQ + l0 + 16 * w) * 128;
    #pragma unroll
    for (int jt = 0; jt < 16; jt++) {
        const int col = 8 * jt + 2 * t;
        *reinterpret_cast<float2*>(ob + (size_t)g * 128 + col) =
            make_float2(C2[jt][0] * inv_lo, C2[jt][1] * inv_lo);
        *reinterpret_cast<float2*>(ob + (size_t)(g + 8) * 128 + col) =
            make_float2(C2[jt][2] * inv_hi, C2[jt][3] * inv_hi);
    }
}

} // anonymous namespace

extern "C" void kernel_launch(void* const* d_in, const int* in_sizes, int n_in,
                              void* d_out, int out_size) {
    const float* q = (const float*)d_in[0];
    const float* k = (const float*)d_in[1];
    const float* v = (const float*)d_in[2];
    float* out = (float*)d_out;

    cudaFuncSetAttribute(axial_attn_kernel,
                         cudaFuncAttributeMaxDynamicSharedMemorySize, SMEM_TOTAL);
    axial_attn_kernel<<<GRID, THREADS, SMEM_TOTAL>>>(q, k, v, out);
}

// round 6
// speedup vs baseline: 1.1620x; 1.0393x over previous
#include <cuda_runtime.h>
#include <cuda_fp16.h>
#include <cstdint>

#define DEVINL __device__ __forceinline__

namespace {

constexpr int BATCH = 32;
constexpr int LSEQ  = 8192;
constexpr int TM    = 64;                    // Q rows per CTA
constexpr int THREADS = 256;                 // 8 warps: 4 row-groups x 2 col-halves
constexpr int GRID = BATCH * (LSEQ / TM);    // 4096

// ---- SMEM layout (bytes). Tiles: 128x128 fp16, 256B row stride, XOR-swizzled.
constexpr int SM_KSUM = 0;                   // 128 floats
constexpr int SM_XCH  = 512;                 // 128 float2 (max,sum) exchange
constexpr int SM_KH   = 2048;
constexpr int SM_KL   = SM_KH + 32768;
constexpr int SM_VH   = SM_KL + 32768;
constexpr int SMEM_TOTAL = SM_VH + 32768;    // 100352 B -> 2 CTAs/SM
// O split-K exchange buffer: reuses KH/KL space (dead after GEMM1)
constexpr int SM_OBUF = SM_KH;
constexpr int OSTR    = 132;                 // floats; 64*132*4 = 33792 B

// byte offset of fp16 element (r, c) in a 128x128 tile; 16B-chunk XOR swizzle
DEVINL uint32_t swz(int r, int c) {
    return (uint32_t)((r << 8) | ((((c >> 3) ^ (r & 7)) << 4) | ((c & 7) << 1)));
}

DEVINL uint32_t smem_u32(const void* p) {
    uint32_t a;
    asm("{ .reg .u64 t; cvta.to.shared.u64 t, %1; cvt.u32.u64 %0, t; }" : "=r"(a) : "l"(p));
    return a;
}

DEVINL uint32_t packh(__half a, __half b) {
    return (uint32_t)__half_as_ushort(a) | ((uint32_t)__half_as_ushort(b) << 16);
}

// split (a,b) into fp16 hi + fp16 lo, packed
DEVINL void split_pack2h(float a, float b, uint32_t& h, uint32_t& l) {
    __half ha = __float2half_rn(a), hb = __float2half_rn(b);
    __half la = __float2half_rn(a - __half2float(ha));
    __half lb = __float2half_rn(b - __half2float(hb));
    h = packh(ha, hb);
    l = packh(la, lb);
}
DEVINL uint32_t pack_hi2(float a, float b) {
    return packh(__float2half_rn(a), __float2half_rn(b));
}

// ldmatrix x4 address: 4 8x8 matrices (rows rbase..+15, 16 cols from c8base*8)
DEVINL uint32_t ldsm_addr(uint32_t tbase, int rbase, int c8base, int lane) {
    int ln = lane & 7, sel = lane >> 3;
    int r  = rbase + ln + ((sel & 1) << 3);
    int c8 = c8base + (sel >> 1);
    return tbase + swz(r, c8 << 3);
}

DEVINL void ldsm4t(uint32_t a[4], uint32_t addr) {
    asm volatile("ldmatrix.sync.aligned.m8n8.x4.trans.shared.b16 {%0,%1,%2,%3}, [%4];"
                 : "=r"(a[0]), "=r"(a[1]), "=r"(a[2]), "=r"(a[3]) : "r"(addr));
}

DEVINL void mma_fp16(float c[4], const uint32_t a[4], uint32_t b0, uint32_t b1) {
    asm volatile(
        "mma.sync.aligned.m16n8k16.row.col.f32.f16.f16.f32 "
        "{%0,%1,%2,%3}, {%4,%5,%6,%7}, {%8,%9}, {%0,%1,%2,%3};"
        : "+f"(c[0]), "+f"(c[1]), "+f"(c[2]), "+f"(c[3])
        : "r"(a[0]), "r"(a[1]), "r"(a[2]), "r"(a[3]), "r"(b0), "r"(b1));
}

__global__ void __launch_bounds__(THREADS, 2)
axial_attn_kernel(const float* __restrict__ q, const float* __restrict__ k,
                  const float* __restrict__ v, float* __restrict__ out) {
    extern __shared__ char smem[];
    const uint32_t sb = smem_u32(smem);
    const int tid  = threadIdx.x;
    const int lane = tid & 31, w = tid >> 5;
    const int wr   = w & 3;        // row group (rows 16*wr .. +15)
    const int sgrp = w >> 2;       // S-column half (0: cols 0-63, 1: 64-127)
    const int g = lane >> 2, t = lane & 3;

    const int b  = blockIdx.x >> 7;
    const int l0 = (blockIdx.x & 127) * TM;

    float* ksum = reinterpret_cast<float*>(smem + SM_KSUM);

    const float* kb = k + (size_t)b * (128 * 128);
    const float* vb = v + (size_t)b * (128 * 128);

    // ---- Q: A-fragment elements straight from GMEM (sector-coalesced) ----
    const float* qrow0 = q + ((size_t)b * LSEQ + l0 + 16 * wr + g) * 128 + 2 * t;
    const float* qrow1 = qrow0 + 8 * 128;
    float2 q0[16], q1[16];
    #pragma unroll
    for (int j = 0; j < 16; j++) {
        q0[j] = *reinterpret_cast<const float2*>(qrow0 + 8 * j);
        q1[j] = *reinterpret_cast<const float2*>(qrow1 + 8 * j);
    }

    // ---- K fill: fp32 -> fp16 hi/lo swizzled SMEM + exact fp32 row sums ----
    {
        const float4* kb4 = reinterpret_cast<const float4*>(kb);
        #pragma unroll 4
        for (int it = 0; it < 16; it++) {
            int e4  = it * THREADS + tid;          // warp covers exactly one row
            int row = e4 >> 5;
            int col = (e4 & 31) << 2;
            float4 tk = kb4[e4];
            uint32_t h01, l01, h23, l23;
            split_pack2h(tk.x, tk.y, h01, l01);
            split_pack2h(tk.z, tk.w, h23, l23);
            uint32_t off = swz(row, col);
            *reinterpret_cast<uint2*>(smem + SM_KH + off) = make_uint2(h01, h23);
            *reinterpret_cast<uint2*>(smem + SM_KL + off) = make_uint2(l01, l23);
            float s = (tk.x + tk.y) + (tk.z + tk.w);
            s += __shfl_xor_sync(0xffffffffu, s, 16);
            s += __shfl_xor_sync(0xffffffffu, s, 8);
            s += __shfl_xor_sync(0xffffffffu, s, 4);
            s += __shfl_xor_sync(0xffffffffu, s, 2);
            s += __shfl_xor_sync(0xffffffffu, s, 1);
            if (lane == 0) ksum[row] = s;
        }
    }
    // ---- V fill: fp16 hi only ----
    {
        const float4* vb4 = reinterpret_cast<const float4*>(vb);
        #pragma unroll 4
        for (int it = 0; it < 16; it++) {
            int e4  = it * THREADS + tid;
            int row = e4 >> 5;
            int col = (e4 & 31) << 2;
            float4 tv = vb4[e4];
            uint32_t off = swz(row, col);
            *reinterpret_cast<uint2*>(smem + SM_VH + off) =
                make_uint2(pack_hi2(tv.x, tv.y), pack_hi2(tv.z, tv.w));
        }
    }

    // ---- qsum (exact fp32, quad-reduced) + Q fragments hi/lo ----
    float qs_lo = 0.f, qs_hi = 0.f;
    #pragma unroll
    for (int j = 0; j < 16; j++) {
        qs_lo += q0[j].x + q0[j].y;
        qs_hi += q1[j].x + q1[j].y;
    }
    qs_lo += __shfl_xor_sync(0xffffffffu, qs_lo, 1);
    qs_lo += __shfl_xor_sync(0xffffffffu, qs_lo, 2);
    qs_hi += __shfl_xor_sync(0xffffffffu, qs_hi, 1);
    qs_hi += __shfl_xor_sync(0xffffffffu, qs_hi, 2);

    uint32_t aqh[8][4], aql[8][4];
    #pragma unroll
    for (int kk = 0; kk < 8; kk++) {
        split_pack2h(q0[2 * kk].x,     q0[2 * kk].y,     aqh[kk][0], aql[kk][0]);
        split_pack2h(q1[2 * kk].x,     q1[2 * kk].y,     aqh[kk][1], aql[kk][1]);
        split_pack2h(q0[2 * kk + 1].x, q0[2 * kk + 1].y, aqh[kk][2], aql[kk][2]);
        split_pack2h(q1[2 * kk + 1].x, q1[2 * kk + 1].y, aqh[kk][3], aql[kk][3]);
    }
    __syncthreads();

    // ---- GEMM1 (this warp's 64 S-cols): S = Qh*Kh + Qh*Kl + Ql*Kh ----
    float C1[8][4];
    #pragma unroll
    for (int jt = 0; jt < 8; jt++)
        #pragma unroll
        for (int i = 0; i < 4; i++) C1[jt][i] = 0.f;

    #pragma unroll
    for (int jp = 0; jp < 4; jp++) {
        const int c8 = 2 * (4 * sgrp + jp);
        #pragma unroll
        for (int kk = 0; kk < 8; kk++) {
            uint32_t bh[4], bl[4];
            ldsm4t(bh, ldsm_addr(sb + SM_KH, 16 * kk, c8, lane));
            ldsm4t(bl, ldsm_addr(sb + SM_KL, 16 * kk, c8, lane));
            mma_fp16(C1[2 * jp],     aqh[kk], bh[0], bh[1]);
            mma_fp16(C1[2 * jp + 1], aqh[kk], bh[2], bh[3]);
            mma_fp16(C1[2 * jp],     aqh[kk], bl[0], bl[1]);
            mma_fp16(C1[2 * jp + 1], aqh[kk], bl[2], bl[3]);
            mma_fp16(C1[2 * jp],     aql[kk], bh[0], bh[1]);
            mma_fp16(C1[2 * jp + 1], aql[kk], bh[2], bh[3]);
        }
    }

    // ---- exact rank-1 term: += qsum[row] * ksum[col] ----
    #pragma unroll
    for (int jt = 0; jt < 8; jt++) {
        float2 ks2 = *reinterpret_cast<const float2*>(ksum + 64 * sgrp + 8 * jt + 2 * t);
        C1[jt][0] += qs_lo * ks2.x;
        C1[jt][1] += qs_lo * ks2.y;
        C1[jt][2] += qs_hi * ks2.x;
        C1[jt][3] += qs_hi * ks2.y;
    }

    // ---- softmax over this half, then merge with partner half ----
    float mlo = -3.4e38f, mhi = -3.4e38f;
    #pragma unroll
    for (int jt = 0; jt < 8; jt++) {
        mlo = fmaxf(mlo, fmaxf(C1[jt][0], C1[jt][1]));
        mhi = fmaxf(mhi, fmaxf(C1[jt][2], C1[jt][3]));
    }
    mlo = fmaxf(mlo, __shfl_xor_sync(0xffffffffu, mlo, 1));
    mlo = fmaxf(mlo, __shfl_xor_sync(0xffffffffu, mlo, 2));
    mhi = fmaxf(mhi, __shfl_xor_sync(0xffffffffu, mhi, 1));
    mhi = fmaxf(mhi, __shfl_xor_sync(0xffffffffu, mhi, 2));

    float slo = 0.f, shi = 0.f;
    #pragma unroll
    for (int jt = 0; jt < 8; jt++) {
        C1[jt][0] = __expf(C1[jt][0] - mlo);
        C1[jt][1] = __expf(C1[jt][1] - mlo);
        C1[jt][2] = __expf(C1[jt][2] - mhi);
        C1[jt][3] = __expf(C1[jt][3] - mhi);
        slo += C1[jt][0] + C1[jt][1];
        shi += C1[jt][2] + C1[jt][3];
    }
    slo += __shfl_xor_sync(0xffffffffu, slo, 1);
    slo += __shfl_xor_sync(0xffffffffu, slo, 2);
    shi += __shfl_xor_sync(0xffffffffu, shi, 1);
    shi += __shfl_xor_sync(0xffffffffu, shi, 2);

    float2* xch = reinterpret_cast<float2*>(smem + SM_XCH);
    if (t == 0) {
        xch[sgrp * 64 + 16 * wr + g]     = make_float2(mlo, slo);
        xch[sgrp * 64 + 16 * wr + g + 8] = make_float2(mhi, shi);
    }
    __syncthreads();
    float2 o_lo = xch[(1 - sgrp) * 64 + 16 * wr + g];
    float2 o_hi = xch[(1 - sgrp) * 64 + 16 * wr + g + 8];
    const float Mlo = fmaxf(mlo, o_lo.x);
    const float Mhi = fmaxf(mhi, o_hi.x);
    const float sc_lo = __expf(mlo - Mlo);
    const float sc_hi = __expf(mhi - Mhi);
    const float inv_lo = 1.0f / (slo * sc_lo + o_lo.y * __expf(o_lo.x - Mlo));
    const float inv_hi = 1.0f / (shi * sc_hi + o_hi.y * __expf(o_hi.x - Mhi));

    // ---- P (scaled to global max) -> A-fragments (fp16 hi/lo) ----
    uint32_t ah[4][4], al[4][4];
    #pragma unroll
    for (int kk = 0; kk < 4; kk++) {
        split_pack2h(C1[2 * kk][0] * sc_lo,     C1[2 * kk][1] * sc_lo,     ah[kk][0], al[kk][0]);
        split_pack2h(C1[2 * kk][2] * sc_hi,     C1[2 * kk][3] * sc_hi,     ah[kk][1], al[kk][1]);
        split_pack2h(C1[2 * kk + 1][0] * sc_lo, C1[2 * kk + 1][1] * sc_lo, ah[kk][2], al[kk][2]);
        split_pack2h(C1[2 * kk + 1][2] * sc_hi, C1[2 * kk + 1][3] * sc_hi, ah[kk][3], al[kk][3]);
    }

    // ---- GEMM2 (split-K over this warp's 64 S-rows): O_part = (Ph+Pl) @ Vh ----
    float C2[16][4];
    #pragma unroll
    for (int jt = 0; jt < 16; jt++)
        #pragma unroll
        for (int i = 0; i < 4; i++) C2[jt][i] = 0.f;

    #pragma unroll
    for (int jp = 0; jp < 8; jp++) {
        #pragma unroll
        for (int kk = 0; kk < 4; kk++) {
            uint32_t bh[4];
            ldsm4t(bh, ldsm_addr(sb + SM_VH, 16 * (4 * sgrp + kk), 2 * jp, lane));
            mma_fp16(C2[2 * jp],     ah[kk], bh[0], bh[1]);
            mma_fp16(C2[2 * jp + 1], ah[kk], bh[2], bh[3]);
            mma_fp16(C2[2 * jp],     al[kk], bh[0], bh[1]);
            mma_fp16(C2[2 * jp + 1], al[kk], bh[2], bh[3]);
        }
    }

    // ---- split-K reduce via SMEM (reusing dead K tiles), then store ----
    float* obuf = reinterpret_cast<float*>(smem + SM_OBUF);
    if (sgrp == 1) {
        #pragma unroll
        for (int jt = 0; jt < 16; jt++) {
            const int col = 8 * jt + 2 * t;
            *reinterpret_cast<float2*>(obuf + (16 * wr + g) * OSTR + col) =
                make_float2(C2[jt][0], C2[jt][1]);
            *reinterpret_cast<float2*>(obuf + (16 * wr + g + 8) * OSTR + col) =
                make_float2(C2[jt][2], C2[jt][3]);
        }
    }
    __syncthreads();
    if (sgrp == 0) {
        float* og = out + ((size_t)b * LSEQ + l0 + 16 * wr) * 128;
        #pragma unroll
        for (int jt = 0; jt < 16; jt++) {
            const int col = 8 * jt + 2 * t;
            float2 p0 = *reinterpret_cast<const float2*>(obuf + (16 * wr + g) * OSTR + col);
            float2 p1 = *reinterpret_cast<const float2*>(obuf + (16 * wr + g + 8) * OSTR + col);
            *reinterpret_cast<float2*>(og + (size_t)g * 128 + col) =
                make_float2((C2[jt][0] + p0.x) * inv_lo, (C2[jt][1] + p0.y) * inv_lo);
            *reinterpret_cast<float2*>(og + (size_t)(g + 8) * 128 + col) =
                make_float2((C2[jt][2] + p1.x) * inv_hi, (C2[jt][3] + p1.y) * inv_hi);
        }
    }
}

} // anonymous namespace

extern "C" void kernel_launch(void* const* d_in, const int* in_sizes, int n_in,
                              void* d_out, int out_size) {
    const float* q = (const float*)d_in[0];
    const float* k = (const float*)d_in[1];
    const float* v = (const float*)d_in[2];
    float* out = (float*)d_out;

    cudaFuncSetAttribute(axial_attn_kernel,
                         cudaFuncAttributeMaxDynamicSharedMemorySize, SMEM_TOTAL);
    axial_attn_kernel<<<GRID, THREADS, SMEM_TOTAL>>>(q, k, v, out);
}

// round 7
// speedup vs baseline: 1.1947x; 1.0281x over previous
#include <cuda_runtime.h>
#include <cuda_fp16.h>
#include <cstdint>

#define DEVINL __device__ __forceinline__

namespace {

constexpr int BATCH = 32;
constexpr int LSEQ  = 8192;
constexpr int TM    = 64;                    // Q rows per tile
constexpr int THREADS = 256;                 // 8 warps: 4 row-groups x 2 S-halves
constexpr int GRID = 296;                    // one full wave @ 2 CTAs/SM
constexpr int TILES_PER_BATCH = LSEQ / TM;   // 128

// ---- SMEM layout (bytes) ----
constexpr int SM_KSUM = 0;                   // 128 floats
constexpr int SM_XCH  = 512;                 // 128 float2 (max,sum)
constexpr int SM_OB   = 1536;                // 64 x 34 floats chunk exchange = 8704
constexpr int SM_KH   = 10240;               // 128x128 fp16, XOR-swizzled
constexpr int SM_KL   = SM_KH + 32768;
constexpr int SM_VH   = SM_KL + 32768;
constexpr int SMEM_TOTAL = SM_VH + 32768;    // 108544 -> 2 CTAs/SM
constexpr int OBSTR  = 34;                   // floats per row in exchange buffer

// byte offset of fp16 element (r, c) in a 128x128 tile; 16B-chunk XOR swizzle
DEVINL uint32_t swz(int r, int c) {
    return (uint32_t)((r << 8) | ((((c >> 3) ^ (r & 7)) << 4) | ((c & 7) << 1)));
}

DEVINL uint32_t smem_u32(const void* p) {
    uint32_t a;
    asm("{ .reg .u64 t; cvta.to.shared.u64 t, %1; cvt.u32.u64 %0, t; }" : "=r"(a) : "l"(p));
    return a;
}

DEVINL uint32_t packh(__half a, __half b) {
    return (uint32_t)__half_as_ushort(a) | ((uint32_t)__half_as_ushort(b) << 16);
}

DEVINL void split_pack2h(float a, float b, uint32_t& h, uint32_t& l) {
    __half ha = __float2half_rn(a), hb = __float2half_rn(b);
    __half la = __float2half_rn(a - __half2float(ha));
    __half lb = __float2half_rn(b - __half2float(hb));
    h = packh(ha, hb);
    l = packh(la, lb);
}
DEVINL uint32_t pack_hi2(float a, float b) {
    return packh(__float2half_rn(a), __float2half_rn(b));
}

DEVINL uint32_t ldsm_addr(uint32_t tbase, int rbase, int c8base, int lane) {
    int ln = lane & 7, sel = lane >> 3;
    int r  = rbase + ln + ((sel & 1) << 3);
    int c8 = c8base + (sel >> 1);
    return tbase + swz(r, c8 << 3);
}

DEVINL void ldsm4t(uint32_t a[4], uint32_t addr) {
    asm volatile("ldmatrix.sync.aligned.m8n8.x4.trans.shared.b16 {%0,%1,%2,%3}, [%4];"
                 : "=r"(a[0]), "=r"(a[1]), "=r"(a[2]), "=r"(a[3]) : "r"(addr));
}

DEVINL void mma_fp16(float c[4], const uint32_t a[4], uint32_t b0, uint32_t b1) {
    asm volatile(
        "mma.sync.aligned.m16n8k16.row.col.f32.f16.f16.f32 "
        "{%0,%1,%2,%3}, {%4,%5,%6,%7}, {%8,%9}, {%0,%1,%2,%3};"
        : "+f"(c[0]), "+f"(c[1]), "+f"(c[2]), "+f"(c[3])
        : "r"(a[0]), "r"(a[1]), "r"(a[2]), "r"(a[3]), "r"(b0), "r"(b1));
}

DEVINL void l2_prefetch(const void* p) {
    asm volatile("prefetch.global.L2 [%0];" :: "l"(p));
}

__global__ void __launch_bounds__(THREADS, 2)
axial_attn_kernel(const float* __restrict__ q, const float* __restrict__ k,
                  const float* __restrict__ v, float* __restrict__ out) {
    extern __shared__ char smem[];
    const uint32_t sb = smem_u32(smem);
    const int tid  = threadIdx.x;
    const int lane = tid & 31, w = tid >> 5;
    const int wr   = w & 3;        // row group (rows 16*wr .. +15)
    const int sgrp = w >> 2;       // S-column half
    const int g = lane >> 2, t = lane & 3;

    // ---- CTA -> (batch, tile chunk). 296 = 8*10 + 24*9 ----
    int bx = blockIdx.x;
    int batch, cidx, ncta;
    if (bx < 80) { batch = bx / 10; cidx = bx - batch * 10; ncta = 10; }
    else { int r = bx - 80; int bb = r / 9; batch = 8 + bb; cidx = r - bb * 9; ncta = 9; }
    const int base = TILES_PER_BATCH / ncta, rem = TILES_PER_BATCH - base * ncta;
    int tstart, tcnt;
    if (cidx < rem) { tcnt = base + 1; tstart = cidx * tcnt; }
    else            { tcnt = base;     tstart = rem * (base + 1) + (cidx - rem) * base; }

    float* ksum = reinterpret_cast<float*>(smem + SM_KSUM);
    float2* xch = reinterpret_cast<float2*>(smem + SM_XCH);
    float* obuf = reinterpret_cast<float*>(smem + SM_OB);

    const float* kb = k + (size_t)batch * (128 * 128);
    const float* vb = v + (size_t)batch * (128 * 128);

    // ======== one-time fill: K (hi/lo + row sums) and V (hi) ========
    {
        const float4* kb4 = reinterpret_cast<const float4*>(kb);
        #pragma unroll 4
        for (int it = 0; it < 16; it++) {
            int e4  = it * THREADS + tid;          // warp covers exactly one row
            int row = e4 >> 5;
            int col = (e4 & 31) << 2;
            float4 tk = kb4[e4];
            uint32_t h01, l01, h23, l23;
            split_pack2h(tk.x, tk.y, h01, l01);
            split_pack2h(tk.z, tk.w, h23, l23);
            uint32_t off = swz(row, col);
            *reinterpret_cast<uint2*>(smem + SM_KH + off) = make_uint2(h01, h23);
            *reinterpret_cast<uint2*>(smem + SM_KL + off) = make_uint2(l01, l23);
            float s = (tk.x + tk.y) + (tk.z + tk.w);
            s += __shfl_xor_sync(0xffffffffu, s, 16);
            s += __shfl_xor_sync(0xffffffffu, s, 8);
            s += __shfl_xor_sync(0xffffffffu, s, 4);
            s += __shfl_xor_sync(0xffffffffu, s, 2);
            s += __shfl_xor_sync(0xffffffffu, s, 1);
            if (lane == 0) ksum[row] = s;
        }
        const float4* vb4 = reinterpret_cast<const float4*>(vb);
        #pragma unroll 4
        for (int it = 0; it < 16; it++) {
            int e4  = it * THREADS + tid;
            int row = e4 >> 5;
            int col = (e4 & 31) << 2;
            float4 tv = vb4[e4];
            uint32_t off = swz(row, col);
            *reinterpret_cast<uint2*>(smem + SM_VH + off) =
                make_uint2(pack_hi2(tv.x, tv.y), pack_hi2(tv.z, tv.w));
        }
    }
    __syncthreads();

    // precomputed ksum values for this warp's S-half (constant across tiles)
    float ksA[8], ksB[8];
    #pragma unroll
    for (int jt = 0; jt < 8; jt++) {
        float2 ks2 = *reinterpret_cast<const float2*>(ksum + 64 * sgrp + 8 * jt + 2 * t);
        ksA[jt] = ks2.x; ksB[jt] = ks2.y;
    }

    // ======== tile loop ========
    for (int ti = 0; ti < tcnt; ti++) {
        const int l0 = (tstart + ti) * TM;

        // ---- Q: A-fragment elements straight from GMEM ----
        const float* qrow0 = q + ((size_t)batch * LSEQ + l0 + 16 * wr + g) * 128 + 2 * t;
        const float* qrow1 = qrow0 + 8 * 128;
        float2 q0[16], q1[16];
        #pragma unroll
        for (int j = 0; j < 16; j++) {
            q0[j] = *reinterpret_cast<const float2*>(qrow0 + 8 * j);
            q1[j] = *reinterpret_cast<const float2*>(qrow1 + 8 * j);
        }

        // ---- L2 prefetch next tile's Q rows ----
        if (ti + 1 < tcnt && t == 0) {
            const float* p0 = qrow0 + (size_t)TM * 128;
            #pragma unroll
            for (int c = 0; c < 4; c++) {
                l2_prefetch(p0 + 32 * c);
                l2_prefetch(p0 + 8 * 128 + 32 * c);
            }
        }

        // ---- qsum (exact fp32, quad-reduced) + Q fragments hi/lo ----
        float qs_lo = 0.f, qs_hi = 0.f;
        #pragma unroll
        for (int j = 0; j < 16; j++) {
            qs_lo += q0[j].x + q0[j].y;
            qs_hi += q1[j].x + q1[j].y;
        }
        qs_lo += __shfl_xor_sync(0xffffffffu, qs_lo, 1);
        qs_lo += __shfl_xor_sync(0xffffffffu, qs_lo, 2);
        qs_hi += __shfl_xor_sync(0xffffffffu, qs_hi, 1);
        qs_hi += __shfl_xor_sync(0xffffffffu, qs_hi, 2);

        uint32_t aqh[8][4], aql[8][4];
        #pragma unroll
        for (int kk = 0; kk < 8; kk++) {
            split_pack2h(q0[2 * kk].x,     q0[2 * kk].y,     aqh[kk][0], aql[kk][0]);
            split_pack2h(q1[2 * kk].x,     q1[2 * kk].y,     aqh[kk][1], aql[kk][1]);
            split_pack2h(q0[2 * kk + 1].x, q0[2 * kk + 1].y, aqh[kk][2], aql[kk][2]);
            split_pack2h(q1[2 * kk + 1].x, q1[2 * kk + 1].y, aqh[kk][3], aql[kk][3]);
        }

        // ---- GEMM1 (this warp's 64 S-cols): S = Qh*Kh + Qh*Kl + Ql*Kh ----
        float C1[8][4];
        #pragma unroll
        for (int jt = 0; jt < 8; jt++)
            #pragma unroll
            for (int i = 0; i < 4; i++) C1[jt][i] = 0.f;

        #pragma unroll
        for (int jp = 0; jp < 4; jp++) {
            const int c8 = 2 * (4 * sgrp + jp);
            #pragma unroll
            for (int kk = 0; kk < 8; kk++) {
                uint32_t bh[4], bl[4];
                ldsm4t(bh, ldsm_addr(sb + SM_KH, 16 * kk, c8, lane));
                ldsm4t(bl, ldsm_addr(sb + SM_KL, 16 * kk, c8, lane));
                mma_fp16(C1[2 * jp],     aqh[kk], bh[0], bh[1]);
                mma_fp16(C1[2 * jp + 1], aqh[kk], bh[2], bh[3]);
                mma_fp16(C1[2 * jp],     aqh[kk], bl[0], bl[1]);
                mma_fp16(C1[2 * jp + 1], aqh[kk], bl[2], bl[3]);
                mma_fp16(C1[2 * jp],     aql[kk], bh[0], bh[1]);
                mma_fp16(C1[2 * jp + 1], aql[kk], bh[2], bh[3]);
            }
        }

        // ---- exact rank-1 term ----
        #pragma unroll
        for (int jt = 0; jt < 8; jt++) {
            C1[jt][0] += qs_lo * ksA[jt];
            C1[jt][1] += qs_lo * ksB[jt];
            C1[jt][2] += qs_hi * ksA[jt];
            C1[jt][3] += qs_hi * ksB[jt];
        }

        // ---- softmax over this half, then merge with partner half ----
        float mlo = -3.4e38f, mhi = -3.4e38f;
        #pragma unroll
        for (int jt = 0; jt < 8; jt++) {
            mlo = fmaxf(mlo, fmaxf(C1[jt][0], C1[jt][1]));
            mhi = fmaxf(mhi, fmaxf(C1[jt][2], C1[jt][3]));
        }
        mlo = fmaxf(mlo, __shfl_xor_sync(0xffffffffu, mlo, 1));
        mlo = fmaxf(mlo, __shfl_xor_sync(0xffffffffu, mlo, 2));
        mhi = fmaxf(mhi, __shfl_xor_sync(0xffffffffu, mhi, 1));
        mhi = fmaxf(mhi, __shfl_xor_sync(0xffffffffu, mhi, 2));

        float slo = 0.f, shi = 0.f;
        #pragma unroll
        for (int jt = 0; jt < 8; jt++) {
            C1[jt][0] = __expf(C1[jt][0] - mlo);
            C1[jt][1] = __expf(C1[jt][1] - mlo);
            C1[jt][2] = __expf(C1[jt][2] - mhi);
            C1[jt][3] = __expf(C1[jt][3] - mhi);
            slo += C1[jt][0] + C1[jt][1];
            shi += C1[jt][2] + C1[jt][3];
        }
        slo += __shfl_xor_sync(0xffffffffu, slo, 1);
        slo += __shfl_xor_sync(0xffffffffu, slo, 2);
        shi += __shfl_xor_sync(0xffffffffu, shi, 1);
        shi += __shfl_xor_sync(0xffffffffu, shi, 2);

        if (t == 0) {
            xch[sgrp * 64 + 16 * wr + g]     = make_float2(mlo, slo);
            xch[sgrp * 64 + 16 * wr + g + 8] = make_float2(mhi, shi);
        }
        __syncthreads();
        float2 o_lo = xch[(1 - sgrp) * 64 + 16 * wr + g];
        float2 o_hi = xch[(1 - sgrp) * 64 + 16 * wr + g + 8];
        const float Mlo = fmaxf(mlo, o_lo.x);
        const float Mhi = fmaxf(mhi, o_hi.x);
        const float sc_lo = __expf(mlo - Mlo);
        const float sc_hi = __expf(mhi - Mhi);
        const float inv_lo = 1.0f / (slo * sc_lo + o_lo.y * __expf(o_lo.x - Mlo));
        const float inv_hi = 1.0f / (shi * sc_hi + o_hi.y * __expf(o_hi.x - Mhi));

        // ---- P (scaled to global max) -> A-fragments (fp16 hi/lo) ----
        uint32_t ah[4][4], al[4][4];
        #pragma unroll
        for (int kk = 0; kk < 4; kk++) {
            split_pack2h(C1[2 * kk][0] * sc_lo,     C1[2 * kk][1] * sc_lo,     ah[kk][0], al[kk][0]);
            split_pack2h(C1[2 * kk][2] * sc_hi,     C1[2 * kk][3] * sc_hi,     ah[kk][1], al[kk][1]);
            split_pack2h(C1[2 * kk + 1][0] * sc_lo, C1[2 * kk + 1][1] * sc_lo, ah[kk][2], al[kk][2]);
            split_pack2h(C1[2 * kk + 1][2] * sc_hi, C1[2 * kk + 1][3] * sc_hi, ah[kk][3], al[kk][3]);
        }

        // ---- GEMM2 (split-K over this warp's 64 S-rows): O_part = (Ph+Pl) @ Vh ----
        float C2[16][4];
        #pragma unroll
        for (int jt = 0; jt < 16; jt++)
            #pragma unroll
            for (int i = 0; i < 4; i++) C2[jt][i] = 0.f;

        #pragma unroll
        for (int jp = 0; jp < 8; jp++) {
            #pragma unroll
            for (int kk = 0; kk < 4; kk++) {
                uint32_t bh[4];
                ldsm4t(bh, ldsm_addr(sb + SM_VH, 16 * (4 * sgrp + kk), 2 * jp, lane));
                mma_fp16(C2[2 * jp],     ah[kk], bh[0], bh[1]);
                mma_fp16(C2[2 * jp + 1], ah[kk], bh[2], bh[3]);
                mma_fp16(C2[2 * jp],     al[kk], bh[0], bh[1]);
                mma_fp16(C2[2 * jp + 1], al[kk], bh[2], bh[3]);
            }
        }

        // ---- chunked split-K reduce (4 chunks of 32 cols) + store ----
        float* og = out + ((size_t)batch * LSEQ + l0 + 16 * wr) * 128;
        #pragma unroll
        for (int c = 0; c < 4; c++) {
            __syncthreads();
            if (sgrp == 1) {
                #pragma unroll
                for (int j = 0; j < 4; j++) {
                    const int jt = 4 * c + j;
                    const int col = 8 * j + 2 * t;
                    *reinterpret_cast<float2*>(obuf + (16 * wr + g) * OBSTR + col) =
                        make_float2(C2[jt][0], C2[jt][1]);
                    *reinterpret_cast<float2*>(obuf + (16 * wr + g + 8) * OBSTR + col) =
                        make_float2(C2[jt][2], C2[jt][3]);
                }
            }
            __syncthreads();
            if (sgrp == 0) {
                #pragma unroll
                for (int j = 0; j < 4; j++) {
                    const int jt = 4 * c + j;
                    const int col = 8 * j + 2 * t;
                    const int colg = 32 * c + col;
                    float2 p0 = *reinterpret_cast<const float2*>(obuf + (16 * wr + g) * OBSTR + col);
                    float2 p1 = *reinterpret_cast<const float2*>(obuf + (16 * wr + g + 8) * OBSTR + col);
                    *reinterpret_cast<float2*>(og + (size_t)g * 128 + colg) =
                        make_float2((C2[jt][0] + p0.x) * inv_lo, (C2[jt][1] + p0.y) * inv_lo);
                    *reinterpret_cast<float2*>(og + (size_t)(g + 8) * 128 + colg) =
                        make_float2((C2[jt][2] + p1.x) * inv_hi, (C2[jt][3] + p1.y) * inv_hi);
                }
            }
        }
    }
}

} // anonymous namespace

extern "C" void kernel_launch(void* const* d_in, const int* in_sizes, int n_in,
                              void* d_out, int out_size) {
    const float* q = (const float*)d_in[0];
    const float* k = (const float*)d_in[1];
    const float* v = (const float*)d_in[2];
    float* out = (float*)d_out;

    cudaFuncSetAttribute(axial_attn_kernel,
                         cudaFuncAttributeMaxDynamicSharedMemorySize, SMEM_TOTAL);
    axial_attn_kernel<<<GRID, THREADS, SMEM_TOTAL>>>(q, k, v, out);
}

// round 9
// speedup vs baseline: 1.4090x; 1.1794x over previous
#include <cuda_runtime.h>
#include <cuda_fp16.h>
#include <cstdint>

#define DEVINL __device__ __forceinline__

namespace {

constexpr int BATCH = 32;
constexpr int LSEQ  = 8192;
constexpr int THREADS = 256;                 // 2 groups x 4 warps
constexpr int GRID = 296;                    // one full wave @ 2 CTAs/SM
constexpr int TILES64_PER_BATCH = 128;       // chunking granularity (64 rows)

// ---- SMEM layout (bytes) ----
constexpr int SM_KSUM = 0;                   // 128 floats
constexpr int SM_XCH  = 512;                 // 2 groups x 64 float2
constexpr int SM_OB   = 1536;                // 2 groups x 32x34 floats = 8704
constexpr int SM_KH   = 10240;               // 128x128 fp16, XOR-swizzled (rows k-permuted)
constexpr int SM_KL   = SM_KH + 32768;
constexpr int SM_VH   = SM_KL + 32768;
constexpr int SMEM_TOTAL = SM_VH + 32768;    // 108544 -> 2 CTAs/SM
constexpr int OBSTR  = 34;                   // floats per row in exchange buffer
constexpr int OBGRP  = 32 * OBSTR;           // floats per group buffer

// byte offset of fp16 element (r, c) in a 128x128 tile; 16B-chunk XOR swizzle
DEVINL uint32_t swz(int r, int c) {
    return (uint32_t)((r << 8) | ((((c >> 3) ^ (r & 7)) << 4) | ((c & 7) << 1)));
}

// k-dim permutation: tile row r' holds original K row kperm-preimage such that
// fragment k-position maps to lane-contiguous Q columns. Within each 16-block:
// orig o = 4t+2b+d  ->  tile pos 8b+2t+d.
DEVINL int kperm(int r) {
    int o = r & 15;
    return (r & 112) | ((o & 2) << 2) | ((o & 12) >> 1) | (o & 1);
}

DEVINL uint32_t smem_u32(const void* p) {
    uint32_t a;
    asm("{ .reg .u64 t; cvta.to.shared.u64 t, %1; cvt.u32.u64 %0, t; }" : "=r"(a) : "l"(p));
    return a;
}

DEVINL uint32_t packh(__half a, __half b) {
    return (uint32_t)__half_as_ushort(a) | ((uint32_t)__half_as_ushort(b) << 16);
}

DEVINL void split_pack2h(float a, float b, uint32_t& h, uint32_t& l) {
    __half ha = __float2half_rn(a), hb = __float2half_rn(b);
    __half la = __float2half_rn(a - __half2float(ha));
    __half lb = __float2half_rn(b - __half2float(hb));
    h = packh(ha, hb);
    l = packh(la, lb);
}
DEVINL uint32_t pack_hi2(float a, float b) {
    return packh(__float2half_rn(a), __float2half_rn(b));
}

DEVINL uint32_t ldsm_addr(uint32_t tbase, int rbase, int c8base, int lane) {
    int ln = lane & 7, sel = lane >> 3;
    int r  = rbase + ln + ((sel & 1) << 3);
    int c8 = c8base + (sel >> 1);
    return tbase + swz(r, c8 << 3);
}

DEVINL void ldsm4t(uint32_t a[4], uint32_t addr) {
    asm volatile("ldmatrix.sync.aligned.m8n8.x4.trans.shared.b16 {%0,%1,%2,%3}, [%4];"
                 : "=r"(a[0]), "=r"(a[1]), "=r"(a[2]), "=r"(a[3]) : "r"(addr));
}

DEVINL void mma_fp16(float c[4], const uint32_t a[4], uint32_t b0, uint32_t b1) {
    asm volatile(
        "mma.sync.aligned.m16n8k16.row.col.f32.f16.f16.f32 "
        "{%0,%1,%2,%3}, {%4,%5,%6,%7}, {%8,%9}, {%0,%1,%2,%3};"
        : "+f"(c[0]), "+f"(c[1]), "+f"(c[2]), "+f"(c[3])
        : "r"(a[0]), "r"(a[1]), "r"(a[2]), "r"(a[3]), "r"(b0), "r"(b1));
}

DEVINL void barg(int id) {
    asm volatile("bar.sync %0, 128;" :: "r"(id) : "memory");
}

__global__ void __launch_bounds__(THREADS, 2)
axial_attn_kernel(const float* __restrict__ q, const float* __restrict__ k,
                  const float* __restrict__ v, float* __restrict__ out) {
    extern __shared__ char smem[];
    const uint32_t sb = smem_u32(smem);
    const int tid  = threadIdx.x;
    const int lane = tid & 31, w = tid >> 5;
    const int grp  = w >> 2;       // independent tile-stream group
    const int wr   = (w >> 1) & 1; // row group within 32-row tile
    const int sgrp = w & 1;        // S-column half
    const int g = lane >> 2, t = lane & 3;

    // ---- CTA -> (batch, 64-row tile chunk). 296 = 8*10 + 24*9 ----
    int bx = blockIdx.x;
    int batch, cidx, ncta;
    if (bx < 80) { batch = bx / 10; cidx = bx - batch * 10; ncta = 10; }
    else { int r = bx - 80; int bb = r / 9; batch = 8 + bb; cidx = r - bb * 9; ncta = 9; }
    const int base = TILES64_PER_BATCH / ncta, rem = TILES64_PER_BATCH - base * ncta;
    int tstart, tcnt;
    if (cidx < rem) { tcnt = base + 1; tstart = cidx * tcnt; }
    else            { tcnt = base;     tstart = rem * (base + 1) + (cidx - rem) * base; }
    // 32-row tiles: group grp handles tiles 2*tstart + 2*i + grp, i in [0, tcnt)

    float*  ksum = reinterpret_cast<float*>(smem + SM_KSUM);
    float2* xch  = reinterpret_cast<float2*>(smem + SM_XCH) + grp * 64;
    float*  obuf = reinterpret_cast<float*>(smem + SM_OB) + grp * OBGRP;

    const float* kb = k + (size_t)batch * (128 * 128);
    const float* vb = v + (size_t)batch * (128 * 128);

    // ======== one-time fill: K (hi/lo, k-permuted rows, + row sums), V (hi) ========
    {
        const float4* kb4 = reinterpret_cast<const float4*>(kb);
        #pragma unroll 4
        for (int it = 0; it < 16; it++) {
            int e4  = it * THREADS + tid;          // warp covers exactly one row
            int row = e4 >> 5;
            int col = (e4 & 31) << 2;
            float4 tk = kb4[e4];
            uint32_t h01, l01, h23, l23;
            split_pack2h(tk.x, tk.y, h01, l01);
            split_pack2h(tk.z, tk.w, h23, l23);
            uint32_t off = swz(kperm(row), col);
            *reinterpret_cast<uint2*>(smem + SM_KH + off) = make_uint2(h01, h23);
            *reinterpret_cast<uint2*>(smem + SM_KL + off) = make_uint2(l01, l23);
            float s = (tk.x + tk.y) + (tk.z + tk.w);
            s += __shfl_xor_sync(0xffffffffu, s, 16);
            s += __shfl_xor_sync(0xffffffffu, s, 8);
            s += __shfl_xor_sync(0xffffffffu, s, 4);
            s += __shfl_xor_sync(0xffffffffu, s, 2);
            s += __shfl_xor_sync(0xffffffffu, s, 1);
            if (lane == 0) ksum[row] = s;
        }
        const float4* vb4 = reinterpret_cast<const float4*>(vb);
        #pragma unroll 4
        for (int it = 0; it < 16; it++) {
            int e4  = it * THREADS + tid;
            int row = e4 >> 5;
            int col = (e4 & 31) << 2;
            float4 tv = vb4[e4];
            uint32_t off = swz(row, col);
            *reinterpret_cast<uint2*>(smem + SM_VH + off) =
                make_uint2(pack_hi2(tv.x, tv.y), pack_hi2(tv.z, tv.w));
        }
    }
    __syncthreads();

    const int barid = 1 + grp;

    // ======== per-group tile loop (32-row tiles) ========
    for (int ti = 0; ti < tcnt; ti++) {
        const int l0 = (2 * tstart + 2 * ti + grp) * 32;

        // ---- Q: one float4 per (rowhalf, kk) IS the A-fragment (k-permuted) ----
        const float* qr0 = q + ((size_t)batch * LSEQ + l0 + 16 * wr + g) * 128 + 4 * t;
        const float* qr1 = qr0 + 8 * 128;
        float4 qf0[8], qf1[8];
        #pragma unroll
        for (int kk = 0; kk < 8; kk++) {
            qf0[kk] = *reinterpret_cast<const float4*>(qr0 + 16 * kk);
            qf1[kk] = *reinterpret_cast<const float4*>(qr1 + 16 * kk);
        }

        // ---- qsum (exact fp32, quad-reduced) ----
        float qs_lo = 0.f, qs_hi = 0.f;
        #pragma unroll
        for (int kk = 0; kk < 8; kk++) {
            qs_lo += (qf0[kk].x + qf0[kk].y) + (qf0[kk].z + qf0[kk].w);
            qs_hi += (qf1[kk].x + qf1[kk].y) + (qf1[kk].z + qf1[kk].w);
        }
        qs_lo += __shfl_xor_sync(0xffffffffu, qs_lo, 1);
        qs_lo += __shfl_xor_sync(0xffffffffu, qs_lo, 2);
        qs_hi += __shfl_xor_sync(0xffffffffu, qs_hi, 1);
        qs_hi += __shfl_xor_sync(0xffffffffu, qs_hi, 2);

        // ---- GEMM1 (kk-outer, transient A frags): S = Qh*Kh + Qh*Kl + Ql*Kh ----
        float C1[8][4];
        #pragma unroll
        for (int jt = 0; jt < 8; jt++)
            #pragma unroll
            for (int i = 0; i < 4; i++) C1[jt][i] = 0.f;

        #pragma unroll
        for (int kk = 0; kk < 8; kk++) {
            uint32_t A_h[4], A_l[4];
            split_pack2h(qf0[kk].x, qf0[kk].y, A_h[0], A_l[0]);
            split_pack2h(qf1[kk].x, qf1[kk].y, A_h[1], A_l[1]);
            split_pack2h(qf0[kk].z, qf0[kk].w, A_h[2], A_l[2]);
            split_pack2h(qf1[kk].z, qf1[kk].w, A_h[3], A_l[3]);
            #pragma unroll
            for (int jp = 0; jp < 4; jp++) {
                const int c8 = 2 * (4 * sgrp + jp);
                uint32_t bh[4], bl[4];
                ldsm4t(bh, ldsm_addr(sb + SM_KH, 16 * kk, c8, lane));
                ldsm4t(bl, ldsm_addr(sb + SM_KL, 16 * kk, c8, lane));
                mma_fp16(C1[2 * jp],     A_h, bh[0], bh[1]);
                mma_fp16(C1[2 * jp + 1], A_h, bh[2], bh[3]);
                mma_fp16(C1[2 * jp],     A_h, bl[0], bl[1]);
                mma_fp16(C1[2 * jp + 1], A_h, bl[2], bl[3]);
                mma_fp16(C1[2 * jp],     A_l, bh[0], bh[1]);
                mma_fp16(C1[2 * jp + 1], A_l, bh[2], bh[3]);
            }
        }

        // ---- exact rank-1 term ----
        #pragma unroll
        for (int jt = 0; jt < 8; jt++) {
            float2 ks2 = *reinterpret_cast<const float2*>(ksum + 64 * sgrp + 8 * jt + 2 * t);
            C1[jt][0] += qs_lo * ks2.x;
            C1[jt][1] += qs_lo * ks2.y;
            C1[jt][2] += qs_hi * ks2.x;
            C1[jt][3] += qs_hi * ks2.y;
        }

        // ---- softmax over this half, merge with partner half (group-scoped) ----
        float mlo = -3.4e38f, mhi = -3.4e38f;
        #pragma unroll
        for (int jt = 0; jt < 8; jt++) {
            mlo = fmaxf(mlo, fmaxf(C1[jt][0], C1[jt][1]));
            mhi = fmaxf(mhi, fmaxf(C1[jt][2], C1[jt][3]));
        }
        mlo = fmaxf(mlo, __shfl_xor_sync(0xffffffffu, mlo, 1));
        mlo = fmaxf(mlo, __shfl_xor_sync(0xffffffffu, mlo, 2));
        mhi = fmaxf(mhi, __shfl_xor_sync(0xffffffffu, mhi, 1));
        mhi = fmaxf(mhi, __shfl_xor_sync(0xffffffffu, mhi, 2));

        float slo = 0.f, shi = 0.f;
        #pragma unroll
        for (int jt = 0; jt < 8; jt++) {
            C1[jt][0] = __expf(C1[jt][0] - mlo);
            C1[jt][1] = __expf(C1[jt][1] - mlo);
            C1[jt][2] = __expf(C1[jt][2] - mhi);
            C1[jt][3] = __expf(C1[jt][3] - mhi);
            slo += C1[jt][0] + C1[jt][1];
            shi += C1[jt][2] + C1[jt][3];
        }
        slo += __shfl_xor_sync(0xffffffffu, slo, 1);
        slo += __shfl_xor_sync(0xffffffffu, slo, 2);
        shi += __shfl_xor_sync(0xffffffffu, shi, 1);
        shi += __shfl_xor_sync(0xffffffffu, shi, 2);

        if (t == 0) {
            xch[sgrp * 32 + 16 * wr + g]     = make_float2(mlo, slo);
            xch[sgrp * 32 + 16 * wr + g + 8] = make_float2(mhi, shi);
        }
        barg(barid);
        float2 o_lo = xch[(1 - sgrp) * 32 + 16 * wr + g];
        float2 o_hi = xch[(1 - sgrp) * 32 + 16 * wr + g + 8];
        const float Mlo = fmaxf(mlo, o_lo.x);
        const float Mhi = fmaxf(mhi, o_hi.x);
        const float sc_lo = __expf(mlo - Mlo);
        const float sc_hi = __expf(mhi - Mhi);
        const float inv_lo = 1.0f / (slo * sc_lo + o_lo.y * __expf(o_lo.x - Mlo));
        const float inv_hi = 1.0f / (shi * sc_hi + o_hi.y * __expf(o_hi.x - Mhi));

        // ---- P (scaled to global max) -> A-fragments (fp16 hi/lo) ----
        uint32_t ah[4][4], al[4][4];
        #pragma unroll
        for (int kk = 0; kk < 4; kk++) {
            split_pack2h(C1[2 * kk][0] * sc_lo,     C1[2 * kk][1] * sc_lo,     ah[kk][0], al[kk][0]);
            split_pack2h(C1[2 * kk][2] * sc_hi,     C1[2 * kk][3] * sc_hi,     ah[kk][1], al[kk][1]);
            split_pack2h(C1[2 * kk + 1][0] * sc_lo, C1[2 * kk + 1][1] * sc_lo, ah[kk][2], al[kk][2]);
            split_pack2h(C1[2 * kk + 1][2] * sc_hi, C1[2 * kk + 1][3] * sc_hi, ah[kk][3], al[kk][3]);
        }

        // ---- GEMM2 (split-K over this warp's 64 S-rows): O_part = (Ph+Pl) @ Vh ----
        float C2[16][4];
        #pragma unroll
        for (int jt = 0; jt < 16; jt++)
            #pragma unroll
            for (int i = 0; i < 4; i++) C2[jt][i] = 0.f;

        #pragma unroll
        for (int jp = 0; jp < 8; jp++) {
            #pragma unroll
            for (int kk = 0; kk < 4; kk++) {
                uint32_t bh[4];
                ldsm4t(bh, ldsm_addr(sb + SM_VH, 16 * (4 * sgrp + kk), 2 * jp, lane));
                mma_fp16(C2[2 * jp],     ah[kk], bh[0], bh[1]);
                mma_fp16(C2[2 * jp + 1], ah[kk], bh[2], bh[3]);
                mma_fp16(C2[2 * jp],     al[kk], bh[0], bh[1]);
                mma_fp16(C2[2 * jp + 1], al[kk], bh[2], bh[3]);
            }
        }

        // ---- chunked split-K reduce (4 chunks of 32 cols, group-scoped) + store ----
        float* og = out + ((size_t)batch * LSEQ + l0 + 16 * wr) * 128;
        #pragma unroll
        for (int c = 0; c < 4; c++) {
            barg(barid);
            if (sgrp == 1) {
                #pragma unroll
                for (int j = 0; j < 4; j++) {
                    const int jt = 4 * c + j;
                    const int col = 8 * j + 2 * t;
                    *reinterpret_cast<float2*>(obuf + (16 * wr + g) * OBSTR + col) =
                        make_float2(C2[jt][0], C2[jt][1]);
                    *reinterpret_cast<float2*>(obuf + (16 * wr + g + 8) * OBSTR + col) =
                        make_float2(C2[jt][2], C2[jt][3]);
                }
            }
            barg(barid);
            if (sgrp == 0) {
                #pragma unroll
                for (int j = 0; j < 4; j++) {
                    const int jt = 4 * c + j;
                    const int col = 8 * j + 2 * t;
                    const int colg = 32 * c + col;
                    float2 p0 = *reinterpret_cast<const float2*>(obuf + (16 * wr + g) * OBSTR + col);
                    float2 p1 = *reinterpret_cast<const float2*>(obuf + (16 * wr + g + 8) * OBSTR + col);
                    *reinterpret_cast<float2*>(og + (size_t)g * 128 + colg) =
                        make_float2((C2[jt][0] + p0.x) * inv_lo, (C2[jt][1] + p0.y) * inv_lo);
                    *reinterpret_cast<float2*>(og + (size_t)(g + 8) * 128 + colg) =
                        make_float2((C2[jt][2] + p1.x) * inv_hi, (C2[jt][3] + p1.y) * inv_hi);
                }
            }
        }
    }
}

} // anonymous namespace

extern "C" void kernel_launch(void* const* d_in, const int* in_sizes, int n_in,
                              void* d_out, int out_size) {
    const float* q = (const float*)d_in[0];
    const float* k = (const float*)d_in[1];
    const float* v = (const float*)d_in[2];
    float* out = (float*)d_out;

    cudaFuncSetAttribute(axial_attn_kernel,
                         cudaFuncAttributeMaxDynamicSharedMemorySize, SMEM_TOTAL);
    axial_attn_kernel<<<GRID, THREADS, SMEM_TOTAL>>>(q, k, v, out);
}

// round 10
// speedup vs baseline: 1.6574x; 1.1763x over previous
#include <cuda_runtime.h>
#include <cuda_fp16.h>
#include <cstdint>

#define DEVINL __device__ __forceinline__

namespace {

constexpr int BATCH = 32;
constexpr int LSEQ  = 8192;
constexpr int THREADS = 256;                 // 2 groups x 4 warps
constexpr int GRID = 296;                    // one full wave @ 2 CTAs/SM
constexpr int TILES64_PER_BATCH = 128;       // chunking granularity (64 rows)

// ---- SMEM layout (bytes) ----
constexpr int SM_KSUM = 0;                   // 128 floats
constexpr int SM_XCH  = 512;                 // 2 groups x 64 float2 = 1024
constexpr int SM_PB   = 2048;                // 2 groups x 4096 (P half-buffer, fp16)
constexpr int SM_KH   = 10240;               // 128x128 fp16, XOR-swizzled (rows k-permuted)
constexpr int SM_KL   = SM_KH + 32768;
constexpr int SM_VH   = SM_KL + 32768;
constexpr int SMEM_TOTAL = SM_VH + 32768;    // 108544 -> 2 CTAs/SM

// byte offset of fp16 element (r, c) in a 128x128 tile (256B rows); XOR swizzle
DEVINL uint32_t swz(int r, int c) {
    return (uint32_t)((r << 8) | ((((c >> 3) ^ (r & 7)) << 4) | ((c & 7) << 1)));
}
// same for a 32x64 fp16 tile (128B rows) — the P half-buffer
DEVINL uint32_t swz2(int r, int c) {
    return (uint32_t)((r << 7) | ((((c >> 3) ^ (r & 7)) << 4) | ((c & 7) << 1)));
}

// k-dim permutation (see R8): orig o = 4t+2b+d -> tile pos 8b+2t+d within 16-block
DEVINL int kperm(int r) {
    int o = r & 15;
    return (r & 112) | ((o & 2) << 2) | ((o & 12) >> 1) | (o & 1);
}

DEVINL uint32_t smem_u32(const void* p) {
    uint32_t a;
    asm("{ .reg .u64 t; cvta.to.shared.u64 t, %1; cvt.u32.u64 %0, t; }" : "=r"(a) : "l"(p));
    return a;
}

DEVINL uint32_t packh(__half a, __half b) {
    return (uint32_t)__half_as_ushort(a) | ((uint32_t)__half_as_ushort(b) << 16);
}

DEVINL void split_pack2h(float a, float b, uint32_t& h, uint32_t& l) {
    __half ha = __float2half_rn(a), hb = __float2half_rn(b);
    __half la = __float2half_rn(a - __half2float(ha));
    __half lb = __float2half_rn(b - __half2float(hb));
    h = packh(ha, hb);
    l = packh(la, lb);
}
DEVINL uint32_t pack_hi2(float a, float b) {
    return packh(__float2half_rn(a), __float2half_rn(b));
}

// ldmatrix x4 address into 256B-row tile
DEVINL uint32_t ldsm_addr(uint32_t tbase, int rbase, int c8base, int lane) {
    int ln = lane & 7, sel = lane >> 3;
    int r  = rbase + ln + ((sel & 1) << 3);
    int c8 = c8base + (sel >> 1);
    return tbase + swz(r, c8 << 3);
}
// ldmatrix x4 address into 128B-row tile (P buffer)
DEVINL uint32_t ldsm_addr2(uint32_t tbase, int rbase, int c8base, int lane) {
    int ln = lane & 7, sel = lane >> 3;
    int r  = rbase + ln + ((sel & 1) << 3);
    int c8 = c8base + (sel >> 1);
    return tbase + swz2(r, c8 << 3);
}

DEVINL void ldsm4(uint32_t a[4], uint32_t addr) {
    asm volatile("ldmatrix.sync.aligned.m8n8.x4.shared.b16 {%0,%1,%2,%3}, [%4];"
                 : "=r"(a[0]), "=r"(a[1]), "=r"(a[2]), "=r"(a[3]) : "r"(addr));
}
DEVINL void ldsm4t(uint32_t a[4], uint32_t addr) {
    asm volatile("ldmatrix.sync.aligned.m8n8.x4.trans.shared.b16 {%0,%1,%2,%3}, [%4];"
                 : "=r"(a[0]), "=r"(a[1]), "=r"(a[2]), "=r"(a[3]) : "r"(addr));
}

DEVINL void mma_fp16(float c[4], const uint32_t a[4], uint32_t b0, uint32_t b1) {
    asm volatile(
        "mma.sync.aligned.m16n8k16.row.col.f32.f16.f16.f32 "
        "{%0,%1,%2,%3}, {%4,%5,%6,%7}, {%8,%9}, {%0,%1,%2,%3};"
        : "+f"(c[0]), "+f"(c[1]), "+f"(c[2]), "+f"(c[3])
        : "r"(a[0]), "r"(a[1]), "r"(a[2]), "r"(a[3]), "r"(b0), "r"(b1));
}

DEVINL void barg(int id) {
    asm volatile("bar.sync %0, 128;" :: "r"(id) : "memory");
}

__global__ void __launch_bounds__(THREADS, 2)
axial_attn_kernel(const float* __restrict__ q, const float* __restrict__ k,
                  const float* __restrict__ v, float* __restrict__ out) {
    extern __shared__ char smem[];
    const uint32_t sb = smem_u32(smem);
    const int tid  = threadIdx.x;
    const int lane = tid & 31, w = tid >> 5;
    const int grp  = w >> 2;       // independent tile-stream group
    const int wr   = (w >> 1) & 1; // row group within 32-row tile
    const int sgrp = w & 1;        // S-half (GEMM1) / d-half (GEMM2)
    const int g = lane >> 2, t = lane & 3;

    // ---- CTA -> (batch, 64-row tile chunk). 296 = 8*10 + 24*9 ----
    int bx = blockIdx.x;
    int batch, cidx, ncta;
    if (bx < 80) { batch = bx / 10; cidx = bx - batch * 10; ncta = 10; }
    else { int r = bx - 80; int bb = r / 9; batch = 8 + bb; cidx = r - bb * 9; ncta = 9; }
    const int base = TILES64_PER_BATCH / ncta, rem = TILES64_PER_BATCH - base * ncta;
    int tstart, tcnt;
    if (cidx < rem) { tcnt = base + 1; tstart = cidx * tcnt; }
    else            { tcnt = base;     tstart = rem * (base + 1) + (cidx - rem) * base; }

    float*  ksum = reinterpret_cast<float*>(smem + SM_KSUM);
    float2* xch  = reinterpret_cast<float2*>(smem + SM_XCH) + grp * 64;
    const uint32_t pb = sb + SM_PB + grp * 4096;

    const float* kb = k + (size_t)batch * (128 * 128);
    const float* vb = v + (size_t)batch * (128 * 128);

    // ======== one-time fill: K (hi/lo, k-permuted rows, + row sums), V (hi) ========
    {
        const float4* kb4 = reinterpret_cast<const float4*>(kb);
        #pragma unroll 4
        for (int it = 0; it < 16; it++) {
            int e4  = it * THREADS + tid;          // warp covers exactly one row
            int row = e4 >> 5;
            int col = (e4 & 31) << 2;
            float4 tk = kb4[e4];
            uint32_t h01, l01, h23, l23;
            split_pack2h(tk.x, tk.y, h01, l01);
            split_pack2h(tk.z, tk.w, h23, l23);
            uint32_t off = swz(kperm(row), col);
            *reinterpret_cast<uint2*>(smem + SM_KH + off) = make_uint2(h01, h23);
            *reinterpret_cast<uint2*>(smem + SM_KL + off) = make_uint2(l01, l23);
            float s = (tk.x + tk.y) + (tk.z + tk.w);
            s += __shfl_xor_sync(0xffffffffu, s, 16);
            s += __shfl_xor_sync(0xffffffffu, s, 8);
            s += __shfl_xor_sync(0xffffffffu, s, 4);
            s += __shfl_xor_sync(0xffffffffu, s, 2);
            s += __shfl_xor_sync(0xffffffffu, s, 1);
            if (lane == 0) ksum[row] = s;
        }
        const float4* vb4 = reinterpret_cast<const float4*>(vb);
        #pragma unroll 4
        for (int it = 0; it < 16; it++) {
            int e4  = it * THREADS + tid;
            int row = e4 >> 5;
            int col = (e4 & 31) << 2;
            float4 tv = vb4[e4];
            uint32_t off = swz(row, col);
            *reinterpret_cast<uint2*>(smem + SM_VH + off) =
                make_uint2(pack_hi2(tv.x, tv.y), pack_hi2(tv.z, tv.w));
        }
    }
    __syncthreads();

    // ksum for this warp's S-half, hoisted to registers (tile-invariant)
    float ksA[8], ksB[8];
    #pragma unroll
    for (int jt = 0; jt < 8; jt++) {
        float2 ks2 = *reinterpret_cast<const float2*>(ksum + 64 * sgrp + 8 * jt + 2 * t);
        ksA[jt] = ks2.x; ksB[jt] = ks2.y;
    }

    const int barid = 1 + grp;

    // ======== per-group tile loop (32-row tiles) ========
    for (int ti = 0; ti < tcnt; ti++) {
        const int l0 = (2 * tstart + 2 * ti + grp) * 32;

        // ---- Q: one float4 per (rowhalf, kk) IS the A-fragment (k-permuted) ----
        const float* qr0 = q + ((size_t)batch * LSEQ + l0 + 16 * wr + g) * 128 + 4 * t;
        const float* qr1 = qr0 + 8 * 128;
        float4 qf0[8], qf1[8];
        #pragma unroll
        for (int kk = 0; kk < 8; kk++) {
            qf0[kk] = *reinterpret_cast<const float4*>(qr0 + 16 * kk);
            qf1[kk] = *reinterpret_cast<const float4*>(qr1 + 16 * kk);
        }

        // ---- qsum (exact fp32, quad-reduced) ----
        float qs_lo = 0.f, qs_hi = 0.f;
        #pragma unroll
        for (int kk = 0; kk < 8; kk++) {
            qs_lo += (qf0[kk].x + qf0[kk].y) + (qf0[kk].z + qf0[kk].w);
            qs_hi += (qf1[kk].x + qf1[kk].y) + (qf1[kk].z + qf1[kk].w);
        }
        qs_lo += __shfl_xor_sync(0xffffffffu, qs_lo, 1);
        qs_lo += __shfl_xor_sync(0xffffffffu, qs_lo, 2);
        qs_hi += __shfl_xor_sync(0xffffffffu, qs_hi, 1);
        qs_hi += __shfl_xor_sync(0xffffffffu, qs_hi, 2);

        // ---- GEMM1 (kk-outer, transient A frags): S = Qh*Kh + Qh*Kl + Ql*Kh ----
        float C1[8][4];
        #pragma unroll
        for (int jt = 0; jt < 8; jt++)
            #pragma unroll
            for (int i = 0; i < 4; i++) C1[jt][i] = 0.f;

        #pragma unroll
        for (int kk = 0; kk < 8; kk++) {
            uint32_t A_h[4], A_l[4];
            split_pack2h(qf0[kk].x, qf0[kk].y, A_h[0], A_l[0]);
            split_pack2h(qf1[kk].x, qf1[kk].y, A_h[1], A_l[1]);
            split_pack2h(qf0[kk].z, qf0[kk].w, A_h[2], A_l[2]);
            split_pack2h(qf1[kk].z, qf1[kk].w, A_h[3], A_l[3]);
            #pragma unroll
            for (int jp = 0; jp < 4; jp++) {
                const int c8 = 2 * (4 * sgrp + jp);
                uint32_t bh[4], bl[4];
                ldsm4t(bh, ldsm_addr(sb + SM_KH, 16 * kk, c8, lane));
                ldsm4t(bl, ldsm_addr(sb + SM_KL, 16 * kk, c8, lane));
                mma_fp16(C1[2 * jp],     A_h, bh[0], bh[1]);
                mma_fp16(C1[2 * jp + 1], A_h, bh[2], bh[3]);
                mma_fp16(C1[2 * jp],     A_h, bl[0], bl[1]);
                mma_fp16(C1[2 * jp + 1], A_h, bl[2], bl[3]);
                mma_fp16(C1[2 * jp],     A_l, bh[0], bh[1]);
                mma_fp16(C1[2 * jp + 1], A_l, bh[2], bh[3]);
            }
        }

        // ---- exact rank-1 term ----
        #pragma unroll
        for (int jt = 0; jt < 8; jt++) {
            C1[jt][0] += qs_lo * ksA[jt];
            C1[jt][1] += qs_lo * ksB[jt];
            C1[jt][2] += qs_hi * ksA[jt];
            C1[jt][3] += qs_hi * ksB[jt];
        }

        // ---- softmax over this half, merge with partner half (group-scoped) ----
        float mlo = -3.4e38f, mhi = -3.4e38f;
        #pragma unroll
        for (int jt = 0; jt < 8; jt++) {
            mlo = fmaxf(mlo, fmaxf(C1[jt][0], C1[jt][1]));
            mhi = fmaxf(mhi, fmaxf(C1[jt][2], C1[jt][3]));
        }
        mlo = fmaxf(mlo, __shfl_xor_sync(0xffffffffu, mlo, 1));
        mlo = fmaxf(mlo, __shfl_xor_sync(0xffffffffu, mlo, 2));
        mhi = fmaxf(mhi, __shfl_xor_sync(0xffffffffu, mhi, 1));
        mhi = fmaxf(mhi, __shfl_xor_sync(0xffffffffu, mhi, 2));

        float slo = 0.f, shi = 0.f;
        #pragma unroll
        for (int jt = 0; jt < 8; jt++) {
            C1[jt][0] = __expf(C1[jt][0] - mlo);
            C1[jt][1] = __expf(C1[jt][1] - mlo);
            C1[jt][2] = __expf(C1[jt][2] - mhi);
            C1[jt][3] = __expf(C1[jt][3] - mhi);
            slo += C1[jt][0] + C1[jt][1];
            shi += C1[jt][2] + C1[jt][3];
        }
        slo += __shfl_xor_sync(0xffffffffu, slo, 1);
        slo += __shfl_xor_sync(0xffffffffu, slo, 2);
        shi += __shfl_xor_sync(0xffffffffu, shi, 1);
        shi += __shfl_xor_sync(0xffffffffu, shi, 2);

        if (t == 0) {
            xch[sgrp * 32 + 16 * wr + g]     = make_float2(mlo, slo);
            xch[sgrp * 32 + 16 * wr + g + 8] = make_float2(mhi, shi);
        }
        barg(barid);
        float2 o_lo = xch[(1 - sgrp) * 32 + 16 * wr + g];
        float2 o_hi = xch[(1 - sgrp) * 32 + 16 * wr + g + 8];
        const float Mlo = fmaxf(mlo, o_lo.x);
        const float Mhi = fmaxf(mhi, o_hi.x);
        const float sc_lo = __expf(mlo - Mlo);
        const float sc_hi = __expf(mhi - Mhi);
        const float inv_lo = 1.0f / (slo * sc_lo + o_lo.y * __expf(o_lo.x - Mlo));
        const float inv_hi = 1.0f / (shi * sc_hi + o_hi.y * __expf(o_hi.x - Mhi));

        // ---- P exchange through fp16 SMEM half-buffer, 2 rounds ----
        // A2[kk] = A-fragment for this warp's 16 rows, global S-block kk
        uint32_t A2[8][4];
        #pragma unroll
        for (int h = 0; h < 2; h++) {
            if (sgrp == h) {
                #pragma unroll
                for (int jt = 0; jt < 8; jt++) {
                    *reinterpret_cast<uint32_t*>(smem + (pb - sb) + swz2(16 * wr + g,     8 * jt + 2 * t)) =
                        pack_hi2(C1[jt][0] * sc_lo, C1[jt][1] * sc_lo);
                    *reinterpret_cast<uint32_t*>(smem + (pb - sb) + swz2(16 * wr + g + 8, 8 * jt + 2 * t)) =
                        pack_hi2(C1[jt][2] * sc_hi, C1[jt][3] * sc_hi);
                }
            }
            barg(barid);
            #pragma unroll
            for (int kkq = 0; kkq < 4; kkq++)
                ldsm4(A2[4 * h + kkq], ldsm_addr2(pb, 16 * wr, 2 * kkq, lane));
            barg(barid);   // buffer free for next round / next tile
        }

        // ---- GEMM2 (d-split, full S contraction): O = Ph @ Vh ----
        float C2[8][4];
        #pragma unroll
        for (int n = 0; n < 8; n++)
            #pragma unroll
            for (int i = 0; i < 4; i++) C2[n][i] = 0.f;

        #pragma unroll
        for (int kk = 0; kk < 8; kk++) {
            #pragma unroll
            for (int jp = 0; jp < 4; jp++) {
                const int c8 = 8 * sgrp + 2 * jp;     // this warp's d-half
                uint32_t bh[4];
                ldsm4t(bh, ldsm_addr(sb + SM_VH, 16 * kk, c8, lane));
                mma_fp16(C2[2 * jp],     A2[kk], bh[0], bh[1]);
                mma_fp16(C2[2 * jp + 1], A2[kk], bh[2], bh[3]);
            }
        }

        // ---- store (normalize here): rows 16wr+g/+8, cols 64*sgrp + 8n + 2t ----
        float* og = out + ((size_t)batch * LSEQ + l0 + 16 * wr) * 128 + 64 * sgrp;
        #pragma unroll
        for (int n = 0; n < 8; n++) {
            const int col = 8 * n + 2 * t;
            *reinterpret_cast<float2*>(og + (size_t)g * 128 + col) =
                make_float2(C2[n][0] * inv_lo, C2[n][1] * inv_lo);
            *reinterpret_cast<float2*>(og + (size_t)(g + 8) * 128 + col) =
                make_float2(C2[n][2] * inv_hi, C2[n][3] * inv_hi);
        }
    }
}

} // anonymous namespace

extern "C" void kernel_launch(void* const* d_in, const int* in_sizes, int n_in,
                              void* d_out, int out_size) {
    const float* q = (const float*)d_in[0];
    const float* k = (const float*)d_in[1];
    const float* v = (const float*)d_in[2];
    float* out = (float*)d_out;

    cudaFuncSetAttribute(axial_attn_kernel,
                         cudaFuncAttributeMaxDynamicSharedMemorySize, SMEM_TOTAL);
    axial_attn_kernel<<<GRID, THREADS, SMEM_TOTAL>>>(q, k, v, out);
}